// round 13
// baseline (speedup 1.0000x reference)
#include <cuda_runtime.h>
#include <cuda_fp16.h>

// Problem constants
#define NNODES   100000
#define NEDGES   30000
#define NPAIRS   1600000
#define DFEAT    64
#define NEG_SLOPE 0.2f

#define ECAP 128     // max members per edge bucket (Poisson(53.3))
#define VCAP 64      // max members per vertex bucket (Poisson(16))

// Packed fp32x2 FMA (sm_100+): d = a*b + c per 32-bit lane
#define FMA2(d, a, b, c) \
    asm("fma.rn.f32x2 %0, %1, %2, %3;" : "=l"(d) : "l"(a), "l"(b), "l"(c))
#define PACK_DUP(out, v) \
    asm("mov.b64 %0, {%1, %1};" : "=l"(out) : "r"(__float_as_uint(v)))
#define UNPACK2(lo, hi, in) \
    asm("mov.b64 {%0, %1}, %2;" : "=r"(lo), "=r"(hi) : "l"(in))

__device__ __forceinline__ unsigned int h2_as_u32(__half2 h)
{
    unsigned int u; memcpy(&u, &h, 4); return u;
}
__device__ __forceinline__ __half2 u32_as_h2(unsigned int u)
{
    __half2 h; memcpy(&h, &u, 4); return h;
}

// Scratch (device globals: allocation-free).
// INVARIANT: g_cur_e / g_cur_v are ZERO at kernel_launch entry.
__device__ int    g_cur_e[NEDGES];
__device__ int    g_cur_v[NNODES];
__device__ int    g_mem_e[NEDGES * ECAP];   // vertex ids bucketed by edge
__device__ int    g_mem_v[NNODES * VCAP];   // edge ids bucketed by vertex
__device__ float  g_A   [NEDGES * DFEAT];   // per-edge input-space accumulators
__device__ float2 g_sdc [NEDGES];           // {sum(degV), count}
__device__ __half g_Xh  [NNODES * DFEAT];   // X staged as fp16
__device__ __half g_Xeh [NEDGES * DFEAT];   // per-edge output features (fp16)

// quarter range: split [0,cnt) into 4 contiguous 4-aligned chunks
__device__ __forceinline__ void quarter_range(int cnt, int q, int& beg, int& end)
{
    int m = (cnt + 3) >> 2;
    m = (m + 3) & ~3;
    beg = q * m; if (beg > cnt) beg = cnt;
    end = beg + m; if (end > cnt) end = cnt;
}

// ---------------------------------------------------------------------------
// K1 (x0h): bucket placement + X0 GEMM + fp16 staging of X.
// ---------------------------------------------------------------------------
__global__ __launch_bounds__(256) void k_x0h(
    const float* __restrict__ X, const float* __restrict__ Ww,
    const float* __restrict__ Wb,
    const int* __restrict__ vertex, const int* __restrict__ edges,
    float* __restrict__ out, int n_rows, int n_pairs)
{
    int tid = threadIdx.x;

    // ---- bucket placement (4x unrolled grid-stride) ----
    {
        int stride = gridDim.x * blockDim.x;
        int i = blockIdx.x * blockDim.x + tid;
        for (; i + 3 * stride < n_pairs; i += 4 * stride) {
            int v0 = vertex[i],            e0 = edges[i];
            int v1 = vertex[i + stride],   e1 = edges[i + stride];
            int v2 = vertex[i + 2*stride], e2 = edges[i + 2*stride];
            int v3 = vertex[i + 3*stride], e3 = edges[i + 3*stride];
            int pe0 = atomicAdd(&g_cur_e[e0], 1);
            int pe1 = atomicAdd(&g_cur_e[e1], 1);
            int pe2 = atomicAdd(&g_cur_e[e2], 1);
            int pe3 = atomicAdd(&g_cur_e[e3], 1);
            int pv0 = atomicAdd(&g_cur_v[v0], 1);
            int pv1 = atomicAdd(&g_cur_v[v1], 1);
            int pv2 = atomicAdd(&g_cur_v[v2], 1);
            int pv3 = atomicAdd(&g_cur_v[v3], 1);
            if (pe0 < ECAP) g_mem_e[e0 * ECAP + pe0] = v0;
            if (pe1 < ECAP) g_mem_e[e1 * ECAP + pe1] = v1;
            if (pe2 < ECAP) g_mem_e[e2 * ECAP + pe2] = v2;
            if (pe3 < ECAP) g_mem_e[e3 * ECAP + pe3] = v3;
            if (pv0 < VCAP) g_mem_v[v0 * VCAP + pv0] = e0;
            if (pv1 < VCAP) g_mem_v[v1 * VCAP + pv1] = e1;
            if (pv2 < VCAP) g_mem_v[v2 * VCAP + pv2] = e2;
            if (pv3 < VCAP) g_mem_v[v3 * VCAP + pv3] = e3;
        }
        for (; i < n_pairs; i += stride) {
            int v = vertex[i], e = edges[i];
            int pe = atomicAdd(&g_cur_e[e], 1);
            if (pe < ECAP) g_mem_e[e * ECAP + pe] = v;
            int pv = atomicAdd(&g_cur_v[v], 1);
            if (pv < VCAP) g_mem_v[v * VCAP + pv] = e;
        }
    }

    // ---- GEMM: X0 = X @ W0^T + b0 ----
    __shared__ float Ws[64 * 68];    // Ws[k*68+o] = W[o][k]
    __shared__ float Xs[64 * 68];    // Xs[r*68+k]
    for (int idx = tid; idx < 1024; idx += 256) {
        int o = idx & 63, i4 = idx >> 6;
        float4 w = ((const float4*)Ww)[o * 16 + i4];
        Ws[(i4 * 4 + 0) * 68 + o] = w.x;
        Ws[(i4 * 4 + 1) * 68 + o] = w.y;
        Ws[(i4 * 4 + 2) * 68 + o] = w.z;
        Ws[(i4 * 4 + 3) * 68 + o] = w.w;
    }
    int row0 = blockIdx.x * 64;
    for (int idx = tid; idx < 1024; idx += 256) {
        int r = idx >> 4, j = idx & 15;
        int row = row0 + r;
        float4 v = make_float4(0.f, 0.f, 0.f, 0.f);
        if (row < n_rows) v = ((const float4*)X)[(size_t)row * 16 + j];
        *(float4*)(Xs + r * 68 + j * 4) = v;
    }
    __syncthreads();

    // fp16 copy of X
    for (int idx = tid; idx < 1024; idx += 256) {
        int r = idx >> 4, j = idx & 15;
        int row = row0 + r;
        if (row < n_rows) {
            float4 v = *(const float4*)(Xs + r * 68 + j * 4);
            uint2 h;
            h.x = h2_as_u32(__floats2half2_rn(v.x, v.y));
            h.y = h2_as_u32(__floats2half2_rn(v.z, v.w));
            ((uint2*)g_Xh)[(size_t)row * 16 + j] = h;
        }
    }

    int tx = tid & 7, ty = tid >> 3;
    int r0 = 2 * ty, r1 = r0 + 1;
    unsigned long long aA0[2] = {0, 0}, aA1[2] = {0, 0};
    unsigned long long aB0[2] = {0, 0}, aB1[2] = {0, 0};
    const float* xr0 = Xs + r0 * 68;
    const float* xr1 = Xs + r1 * 68;
#pragma unroll
    for (int kk = 0; kk < 16; kk++) {
        float4 xa = *(const float4*)(xr0 + kk * 4);
        float4 xb = *(const float4*)(xr1 + kk * 4);
#pragma unroll
        for (int m = 0; m < 4; m++) {
            int k = kk * 4 + m;
            ulonglong2 wA = *(const ulonglong2*)(Ws + k * 68 + tx * 4);
            ulonglong2 wB = *(const ulonglong2*)(Ws + k * 68 + 32 + tx * 4);
            float x0v = (m == 0) ? xa.x : (m == 1) ? xa.y : (m == 2) ? xa.z : xa.w;
            float x1v = (m == 0) ? xb.x : (m == 1) ? xb.y : (m == 2) ? xb.z : xb.w;
            unsigned long long p0, p1;
            PACK_DUP(p0, x0v);
            PACK_DUP(p1, x1v);
            FMA2(aA0[0], p0, wA.x, aA0[0]);
            FMA2(aA0[1], p0, wA.y, aA0[1]);
            FMA2(aB0[0], p0, wB.x, aB0[0]);
            FMA2(aB0[1], p0, wB.y, aB0[1]);
            FMA2(aA1[0], p1, wA.x, aA1[0]);
            FMA2(aA1[1], p1, wA.y, aA1[1]);
            FMA2(aB1[0], p1, wB.x, aB1[0]);
            FMA2(aB1[1], p1, wB.y, aB1[1]);
        }
    }
    int oA = tx * 4, oB = 32 + tx * 4;
#pragma unroll
    for (int rr = 0; rr < 2; rr++) {
        int row = row0 + ((rr == 0) ? r0 : r1);
        if (row >= n_rows) continue;
        unsigned long long* accA = (rr == 0) ? aA0 : aA1;
        unsigned long long* accB = (rr == 0) ? aB0 : aB1;
        float* orow = out + (size_t)row * 64;
#pragma unroll
        for (int j = 0; j < 2; j++) {
            unsigned int lo, hi;
            UNPACK2(lo, hi, accA[j]);
            float2 s;
            s.x = __uint_as_float(lo) + Wb[oA + 2 * j + 0];
            s.y = __uint_as_float(hi) + Wb[oA + 2 * j + 1];
            *(float2*)(orow + oA + 2 * j) = s;
            UNPACK2(lo, hi, accB[j]);
            s.x = __uint_as_float(lo) + Wb[oB + 2 * j + 0];
            s.y = __uint_as_float(hi) + Wb[oB + 2 * j + 1];
            *(float2*)(orow + oB + 2 * j) = s;
        }
    }
}

// ---------------------------------------------------------------------------
// K_agg_e: warp per edge, FOUR 8-lane streams, uint4 (8-feature) gathers.
// ---------------------------------------------------------------------------
__global__ __launch_bounds__(256) void k_agg_e(const float* __restrict__ degV)
{
    const uint4* Xh = (const uint4*)g_Xh;   // 8 x 16B per row
    int e    = (blockIdx.x * blockDim.x + threadIdx.x) >> 5;  // grid exact
    int lane = threadIdx.x & 31;
    int q    = lane >> 3;
    int l8   = lane & 7;
    int t = e / 10000;
    const float* degT = degV + t * NNODES;
    const int* mem = g_mem_e + (size_t)e * ECAP;
    int cnt = g_cur_e[e];
    if (cnt > ECAP) cnt = ECAP;
    int beg, end;
    quarter_range(cnt, q, beg, end);
    float acc[8];
#pragma unroll
    for (int j = 0; j < 8; j++) acc[j] = 0.f;
    float sd = 0.f;
    int i = beg;
    for (; i + 3 < end; i += 4) {
        int4 vv = *(const int4*)(mem + i);          // 1 LDG.128
        float d0 = degT[vv.x], d1 = degT[vv.y], d2 = degT[vv.z], d3 = degT[vv.w];
        uint4 u0 = Xh[(size_t)vv.x * 8 + l8];
        uint4 u1 = Xh[(size_t)vv.y * 8 + l8];
        uint4 u2 = Xh[(size_t)vv.z * 8 + l8];
        uint4 u3 = Xh[(size_t)vv.w * 8 + l8];
        float2 f;
#define ACCME(u, d) \
        f = __half22float2(u32_as_h2(u.x)); acc[0] += d * f.x; acc[1] += d * f.y; \
        f = __half22float2(u32_as_h2(u.y)); acc[2] += d * f.x; acc[3] += d * f.y; \
        f = __half22float2(u32_as_h2(u.z)); acc[4] += d * f.x; acc[5] += d * f.y; \
        f = __half22float2(u32_as_h2(u.w)); acc[6] += d * f.x; acc[7] += d * f.y;
        ACCME(u0, d0)
        ACCME(u1, d1)
        ACCME(u2, d2)
        ACCME(u3, d3)
        sd += d0 + d1 + d2 + d3;
    }
    for (; i < end; i++) {
        int v = mem[i];
        float d = degT[v];
        uint4 u = Xh[(size_t)v * 8 + l8];
        float2 f;
        ACCME(u, d)
        sd += d;
    }
#undef ACCME
    // combine 4 streams
#pragma unroll
    for (int j = 0; j < 8; j++) {
        acc[j] += __shfl_xor_sync(0xFFFFFFFFu, acc[j], 8);
        acc[j] += __shfl_xor_sync(0xFFFFFFFFu, acc[j], 16);
    }
    sd += __shfl_xor_sync(0xFFFFFFFFu, sd, 8);
    sd += __shfl_xor_sync(0xFFFFFFFFu, sd, 16);
    if (q == 0) {
        float4* arow = (float4*)g_A + (size_t)e * 16;
        arow[l8 * 2 + 0] = make_float4(acc[0], acc[1], acc[2], acc[3]);
        arow[l8 * 2 + 1] = make_float4(acc[4], acc[5], acc[6], acc[7]);
        if (l8 == 0) {
            g_sdc[e] = make_float2(sd, (float)cnt);
            g_cur_e[e] = 0;   // restore zero invariant
        }
    }
}

// ---------------------------------------------------------------------------
// K_edge: Xe[e] = (W_{t+1} @ A[e] + b*sd[e]) / max(cnt,1). Writes fp16 Xe.
// ---------------------------------------------------------------------------
__global__ __launch_bounds__(256) void k_edge(
    const float* __restrict__ Ww, const float* __restrict__ Wb)
{
    const int CHUNKS = 157;
    int t     = blockIdx.x / CHUNKS;
    int chunk = blockIdx.x % CHUNKS;
    int base  = t * 10000 + chunk * 64;
    int limit = (t + 1) * 10000;

    __shared__ float Ws[64 * 68];
    __shared__ float As[64 * 68];
    const float* W = Ww + (size_t)(t + 1) * 4096;
    const float* b = Wb + (size_t)(t + 1) * 64;
    int tid = threadIdx.x;
    for (int idx = tid; idx < 1024; idx += 256) {
        int o = idx & 63, i4 = idx >> 6;
        float4 w = ((const float4*)W)[o * 16 + i4];
        Ws[(i4 * 4 + 0) * 68 + o] = w.x;
        Ws[(i4 * 4 + 1) * 68 + o] = w.y;
        Ws[(i4 * 4 + 2) * 68 + o] = w.z;
        Ws[(i4 * 4 + 3) * 68 + o] = w.w;
    }
    for (int idx = tid; idx < 1024; idx += 256) {
        int r = idx >> 4, j = idx & 15;
        int e = base + r;
        float4 v = make_float4(0.f, 0.f, 0.f, 0.f);
        if (e < limit) v = ((const float4*)g_A)[(size_t)e * 16 + j];
        *(float4*)(As + r * 68 + j * 4) = v;
    }
    __syncthreads();

    int tx = tid & 7, ty = tid >> 3;
    int r0 = 2 * ty, r1 = r0 + 1;
    unsigned long long aA0[2] = {0, 0}, aA1[2] = {0, 0};
    unsigned long long aB0[2] = {0, 0}, aB1[2] = {0, 0};
    const float* xr0 = As + r0 * 68;
    const float* xr1 = As + r1 * 68;
#pragma unroll
    for (int kk = 0; kk < 16; kk++) {
        float4 xa = *(const float4*)(xr0 + kk * 4);
        float4 xb = *(const float4*)(xr1 + kk * 4);
#pragma unroll
        for (int m = 0; m < 4; m++) {
            int k = kk * 4 + m;
            ulonglong2 wA = *(const ulonglong2*)(Ws + k * 68 + tx * 4);
            ulonglong2 wB = *(const ulonglong2*)(Ws + k * 68 + 32 + tx * 4);
            float x0v = (m == 0) ? xa.x : (m == 1) ? xa.y : (m == 2) ? xa.z : xa.w;
            float x1v = (m == 0) ? xb.x : (m == 1) ? xb.y : (m == 2) ? xb.z : xb.w;
            unsigned long long p0, p1;
            PACK_DUP(p0, x0v);
            PACK_DUP(p1, x1v);
            FMA2(aA0[0], p0, wA.x, aA0[0]);
            FMA2(aA0[1], p0, wA.y, aA0[1]);
            FMA2(aB0[0], p0, wB.x, aB0[0]);
            FMA2(aB0[1], p0, wB.y, aB0[1]);
            FMA2(aA1[0], p1, wA.x, aA1[0]);
            FMA2(aA1[1], p1, wA.y, aA1[1]);
            FMA2(aB1[0], p1, wB.x, aB1[0]);
            FMA2(aB1[1], p1, wB.y, aB1[1]);
        }
    }
    int oA = tx * 4, oB = 32 + tx * 4;
#pragma unroll
    for (int rr = 0; rr < 2; rr++) {
        int e = base + ((rr == 0) ? r0 : r1);
        if (e >= limit) continue;
        float2 sdc = g_sdc[e];
        float sd  = sdc.x;
        float inv = 1.0f / fmaxf(sdc.y, 1.0f);
        unsigned long long* accA = (rr == 0) ? aA0 : aA1;
        unsigned long long* accB = (rr == 0) ? aB0 : aB1;
        __half* orow = g_Xeh + (size_t)e * 64;
        unsigned int lo, hi;
        float sx, sy;
        UNPACK2(lo, hi, accA[0]);
        sx = (__uint_as_float(lo) + b[oA + 0] * sd) * inv;
        sy = (__uint_as_float(hi) + b[oA + 1] * sd) * inv;
        *(__half2*)(orow + oA + 0) = __floats2half2_rn(sx, sy);
        UNPACK2(lo, hi, accA[1]);
        sx = (__uint_as_float(lo) + b[oA + 2] * sd) * inv;
        sy = (__uint_as_float(hi) + b[oA + 3] * sd) * inv;
        *(__half2*)(orow + oA + 2) = __floats2half2_rn(sx, sy);
        UNPACK2(lo, hi, accB[0]);
        sx = (__uint_as_float(lo) + b[oB + 0] * sd) * inv;
        sy = (__uint_as_float(hi) + b[oB + 1] * sd) * inv;
        *(__half2*)(orow + oB + 0) = __floats2half2_rn(sx, sy);
        UNPACK2(lo, hi, accB[1]);
        sx = (__uint_as_float(lo) + b[oB + 2] * sd) * inv;
        sy = (__uint_as_float(hi) + b[oB + 3] * sd) * inv;
        *(__half2*)(orow + oB + 2) = __floats2half2_rn(sx, sy);
    }
}

// ---------------------------------------------------------------------------
// K_agg_v: warp per vertex, FOUR 8-lane streams, uint4 gathers,
// pairwise HADD2 tree. out[v] = lrelu(l2norm(X0[v] + sum)).
// ---------------------------------------------------------------------------
__global__ __launch_bounds__(256) void k_agg_v(float* __restrict__ out)
{
    const uint4* Xe = (const uint4*)g_Xeh;
    int v    = (blockIdx.x * blockDim.x + threadIdx.x) >> 5;
    int lane = threadIdx.x & 31;
    int q    = lane >> 3;
    int l8   = lane & 7;
    const int* mem = g_mem_v + (size_t)v * VCAP;
    int cnt = g_cur_v[v];
    if (cnt > VCAP) cnt = VCAP;
    int beg, end;
    quarter_range(cnt, q, beg, end);
    float acc[8];
#pragma unroll
    for (int j = 0; j < 8; j++) acc[j] = 0.f;
    int i = beg;
    for (; i + 3 < end; i += 4) {
        int4 ee = *(const int4*)(mem + i);          // 1 LDG.128
        uint4 u0 = Xe[(size_t)ee.x * 8 + l8];
        uint4 u1 = Xe[(size_t)ee.y * 8 + l8];
        uint4 u2 = Xe[(size_t)ee.z * 8 + l8];
        uint4 u3 = Xe[(size_t)ee.w * 8 + l8];
        // pairwise fp16 adds, then convert+add
        __half2 s0 = __hadd2(u32_as_h2(u0.x), u32_as_h2(u1.x));
        __half2 s1 = __hadd2(u32_as_h2(u0.y), u32_as_h2(u1.y));
        __half2 s2 = __hadd2(u32_as_h2(u0.z), u32_as_h2(u1.z));
        __half2 s3 = __hadd2(u32_as_h2(u0.w), u32_as_h2(u1.w));
        __half2 t0 = __hadd2(u32_as_h2(u2.x), u32_as_h2(u3.x));
        __half2 t1 = __hadd2(u32_as_h2(u2.y), u32_as_h2(u3.y));
        __half2 t2 = __hadd2(u32_as_h2(u2.z), u32_as_h2(u3.z));
        __half2 t3 = __hadd2(u32_as_h2(u2.w), u32_as_h2(u3.w));
        float2 f;
        f = __half22float2(s0); acc[0] += f.x; acc[1] += f.y;
        f = __half22float2(s1); acc[2] += f.x; acc[3] += f.y;
        f = __half22float2(s2); acc[4] += f.x; acc[5] += f.y;
        f = __half22float2(s3); acc[6] += f.x; acc[7] += f.y;
        f = __half22float2(t0); acc[0] += f.x; acc[1] += f.y;
        f = __half22float2(t1); acc[2] += f.x; acc[3] += f.y;
        f = __half22float2(t2); acc[4] += f.x; acc[5] += f.y;
        f = __half22float2(t3); acc[6] += f.x; acc[7] += f.y;
    }
    for (; i < end; i++) {
        int e = mem[i];
        uint4 u = Xe[(size_t)e * 8 + l8];
        float2 f;
        f = __half22float2(u32_as_h2(u.x)); acc[0] += f.x; acc[1] += f.y;
        f = __half22float2(u32_as_h2(u.y)); acc[2] += f.x; acc[3] += f.y;
        f = __half22float2(u32_as_h2(u.z)); acc[4] += f.x; acc[5] += f.y;
        f = __half22float2(u32_as_h2(u.w)); acc[6] += f.x; acc[7] += f.y;
    }
    // combine 4 streams
#pragma unroll
    for (int j = 0; j < 8; j++) {
        acc[j] += __shfl_xor_sync(0xFFFFFFFFu, acc[j], 8);
        acc[j] += __shfl_xor_sync(0xFFFFFFFFu, acc[j], 16);
    }
    // add X0 (all lanes hold identical stream-sums now; add same slice)
    const float4* xrow = (const float4*)out + (size_t)v * 16;
    float4 x0a = xrow[l8 * 2 + 0];
    float4 x0b = xrow[l8 * 2 + 1];
    acc[0] += x0a.x; acc[1] += x0a.y; acc[2] += x0a.z; acc[3] += x0a.w;
    acc[4] += x0b.x; acc[5] += x0b.y; acc[6] += x0b.z; acc[7] += x0b.w;
    // L2 norm across 64 features: per-lane partial (8 vals) + reduce over l8
    float ss = 0.f;
#pragma unroll
    for (int j = 0; j < 8; j++) ss += acc[j] * acc[j];
    ss += __shfl_xor_sync(0xFFFFFFFFu, ss, 1);
    ss += __shfl_xor_sync(0xFFFFFFFFu, ss, 2);
    ss += __shfl_xor_sync(0xFFFFFFFFu, ss, 4);
    float rn = sqrtf(ss);
    float sc = (rn == 0.0f) ? 0.0f : 1.0f / rn;
#pragma unroll
    for (int j = 0; j < 8; j++) {
        float x = acc[j] * sc;
        acc[j] = (x >= 0.f) ? x : NEG_SLOPE * x;
    }
    if (q == 0) {
        float4* orow = (float4*)out + (size_t)v * 16;
        orow[l8 * 2 + 0] = make_float4(acc[0], acc[1], acc[2], acc[3]);
        orow[l8 * 2 + 1] = make_float4(acc[4], acc[5], acc[6], acc[7]);
        if (l8 == 0) g_cur_v[v] = 0;   // restore zero invariant
    }
}

// ---------------------------------------------------------------------------
extern "C" void kernel_launch(void* const* d_in, const int* in_sizes, int n_in,
                              void* d_out, int out_size)
{
    const float* X      = (const float*)d_in[0];   // [100000, 64] f32
    const float* degV   = (const float*)d_in[1];   // [3, 100000, 1] f32
    const float* Ww     = (const float*)d_in[2];   // [4, 64, 64] f32
    const float* Wb     = (const float*)d_in[3];   // [4, 64] f32
    const int*   vertex = (const int*)d_in[4];     // [1.6M] int32
    const int*   edges  = (const int*)d_in[5];     // [1.6M] int32
    float*       out    = (float*)d_out;           // [100000, 64] f32

    int n_pairs = in_sizes[4];

    k_x0h  <<<(NNODES + 63) / 64, 256>>>(X, Ww, Wb, vertex, edges, out, NNODES, n_pairs);
    k_agg_e<<<(NEDGES * 32) / 256, 256>>>(degV);
    k_edge <<<3 * 157, 256>>>(Ww, Wb);
    k_agg_v<<<(NNODES * 32) / 256, 256>>>(out);
}

// round 14
// speedup vs baseline: 1.5830x; 1.5830x over previous
#include <cuda_runtime.h>
#include <cuda_fp16.h>

// Problem constants
#define NNODES   100000
#define NEDGES   30000
#define NPAIRS   1600000
#define DFEAT    64
#define NEG_SLOPE 0.2f

#define ECAP 128     // max members per edge bucket (Poisson(53.3))
#define VCAP 64      // max members per vertex bucket (Poisson(16))

// Packed fp32x2 FMA (sm_100+): d = a*b + c per 32-bit lane
#define FMA2(d, a, b, c) \
    asm("fma.rn.f32x2 %0, %1, %2, %3;" : "=l"(d) : "l"(a), "l"(b), "l"(c))
#define PACK_DUP(out, v) \
    asm("mov.b64 %0, {%1, %1};" : "=l"(out) : "r"(__float_as_uint(v)))
#define UNPACK2(lo, hi, in) \
    asm("mov.b64 {%0, %1}, %2;" : "=r"(lo), "=r"(hi) : "l"(in))

__device__ __forceinline__ unsigned int h2_as_u32(__half2 h)
{
    unsigned int u; memcpy(&u, &h, 4); return u;
}
__device__ __forceinline__ __half2 u32_as_h2(unsigned int u)
{
    __half2 h; memcpy(&h, &u, 4); return h;
}

// Scratch (device globals: allocation-free).
// INVARIANT: g_cur_e / g_cur_v are ZERO at kernel_launch entry.
__device__ int    g_cur_e[NEDGES];
__device__ int    g_cur_v[NNODES];
__device__ int    g_mem_e[NEDGES * ECAP];   // vertex ids bucketed by edge
__device__ int    g_mem_v[NNODES * VCAP];   // edge ids bucketed by vertex
__device__ float  g_A   [NEDGES * DFEAT];   // per-edge input-space accumulators
__device__ float2 g_sdc [NEDGES];           // {sum(degV), count}
__device__ __half g_Xh  [NNODES * DFEAT];   // X staged as fp16
__device__ __half g_Xeh [NEDGES * DFEAT];   // per-edge output features (fp16)

// split [0,cnt) into two contiguous 4-aligned halves
__device__ __forceinline__ void half_range(int cnt, int half_, int& beg, int& end)
{
    int m = ((cnt + 1) >> 1);
    m = (m + 3) & ~3;
    if (m > cnt) m = cnt;
    beg = half_ ? m : 0;
    end = half_ ? cnt : m;
}

// ---------------------------------------------------------------------------
// K1 (x0h): bucket placement + X0 GEMM + fp16 staging of X.
// ---------------------------------------------------------------------------
__global__ __launch_bounds__(256) void k_x0h(
    const float* __restrict__ X, const float* __restrict__ Ww,
    const float* __restrict__ Wb,
    const int* __restrict__ vertex, const int* __restrict__ edges,
    float* __restrict__ out, int n_rows, int n_pairs)
{
    int tid = threadIdx.x;

    // ---- bucket placement (4x unrolled grid-stride) ----
    {
        int stride = gridDim.x * blockDim.x;
        int i = blockIdx.x * blockDim.x + tid;
        for (; i + 3 * stride < n_pairs; i += 4 * stride) {
            int v0 = vertex[i],            e0 = edges[i];
            int v1 = vertex[i + stride],   e1 = edges[i + stride];
            int v2 = vertex[i + 2*stride], e2 = edges[i + 2*stride];
            int v3 = vertex[i + 3*stride], e3 = edges[i + 3*stride];
            int pe0 = atomicAdd(&g_cur_e[e0], 1);
            int pe1 = atomicAdd(&g_cur_e[e1], 1);
            int pe2 = atomicAdd(&g_cur_e[e2], 1);
            int pe3 = atomicAdd(&g_cur_e[e3], 1);
            int pv0 = atomicAdd(&g_cur_v[v0], 1);
            int pv1 = atomicAdd(&g_cur_v[v1], 1);
            int pv2 = atomicAdd(&g_cur_v[v2], 1);
            int pv3 = atomicAdd(&g_cur_v[v3], 1);
            if (pe0 < ECAP) g_mem_e[e0 * ECAP + pe0] = v0;
            if (pe1 < ECAP) g_mem_e[e1 * ECAP + pe1] = v1;
            if (pe2 < ECAP) g_mem_e[e2 * ECAP + pe2] = v2;
            if (pe3 < ECAP) g_mem_e[e3 * ECAP + pe3] = v3;
            if (pv0 < VCAP) g_mem_v[v0 * VCAP + pv0] = e0;
            if (pv1 < VCAP) g_mem_v[v1 * VCAP + pv1] = e1;
            if (pv2 < VCAP) g_mem_v[v2 * VCAP + pv2] = e2;
            if (pv3 < VCAP) g_mem_v[v3 * VCAP + pv3] = e3;
        }
        for (; i < n_pairs; i += stride) {
            int v = vertex[i], e = edges[i];
            int pe = atomicAdd(&g_cur_e[e], 1);
            if (pe < ECAP) g_mem_e[e * ECAP + pe] = v;
            int pv = atomicAdd(&g_cur_v[v], 1);
            if (pv < VCAP) g_mem_v[v * VCAP + pv] = e;
        }
    }

    // ---- GEMM: X0 = X @ W0^T + b0 ----
    __shared__ float Ws[64 * 68];    // Ws[k*68+o] = W[o][k]
    __shared__ float Xs[64 * 68];    // Xs[r*68+k]
    for (int idx = tid; idx < 1024; idx += 256) {
        int o = idx & 63, i4 = idx >> 6;
        float4 w = ((const float4*)Ww)[o * 16 + i4];
        Ws[(i4 * 4 + 0) * 68 + o] = w.x;
        Ws[(i4 * 4 + 1) * 68 + o] = w.y;
        Ws[(i4 * 4 + 2) * 68 + o] = w.z;
        Ws[(i4 * 4 + 3) * 68 + o] = w.w;
    }
    int row0 = blockIdx.x * 64;
    for (int idx = tid; idx < 1024; idx += 256) {
        int r = idx >> 4, j = idx & 15;
        int row = row0 + r;
        float4 v = make_float4(0.f, 0.f, 0.f, 0.f);
        if (row < n_rows) v = ((const float4*)X)[(size_t)row * 16 + j];
        *(float4*)(Xs + r * 68 + j * 4) = v;
    }
    __syncthreads();

    // fp16 copy of X
    for (int idx = tid; idx < 1024; idx += 256) {
        int r = idx >> 4, j = idx & 15;
        int row = row0 + r;
        if (row < n_rows) {
            float4 v = *(const float4*)(Xs + r * 68 + j * 4);
            uint2 h;
            h.x = h2_as_u32(__floats2half2_rn(v.x, v.y));
            h.y = h2_as_u32(__floats2half2_rn(v.z, v.w));
            ((uint2*)g_Xh)[(size_t)row * 16 + j] = h;
        }
    }

    int tx = tid & 7, ty = tid >> 3;
    int r0 = 2 * ty, r1 = r0 + 1;
    unsigned long long aA0[2] = {0, 0}, aA1[2] = {0, 0};
    unsigned long long aB0[2] = {0, 0}, aB1[2] = {0, 0};
    const float* xr0 = Xs + r0 * 68;
    const float* xr1 = Xs + r1 * 68;
#pragma unroll
    for (int kk = 0; kk < 16; kk++) {
        float4 xa = *(const float4*)(xr0 + kk * 4);
        float4 xb = *(const float4*)(xr1 + kk * 4);
#pragma unroll
        for (int m = 0; m < 4; m++) {
            int k = kk * 4 + m;
            ulonglong2 wA = *(const ulonglong2*)(Ws + k * 68 + tx * 4);
            ulonglong2 wB = *(const ulonglong2*)(Ws + k * 68 + 32 + tx * 4);
            float x0v = (m == 0) ? xa.x : (m == 1) ? xa.y : (m == 2) ? xa.z : xa.w;
            float x1v = (m == 0) ? xb.x : (m == 1) ? xb.y : (m == 2) ? xb.z : xb.w;
            unsigned long long p0, p1;
            PACK_DUP(p0, x0v);
            PACK_DUP(p1, x1v);
            FMA2(aA0[0], p0, wA.x, aA0[0]);
            FMA2(aA0[1], p0, wA.y, aA0[1]);
            FMA2(aB0[0], p0, wB.x, aB0[0]);
            FMA2(aB0[1], p0, wB.y, aB0[1]);
            FMA2(aA1[0], p1, wA.x, aA1[0]);
            FMA2(aA1[1], p1, wA.y, aA1[1]);
            FMA2(aB1[0], p1, wB.x, aB1[0]);
            FMA2(aB1[1], p1, wB.y, aB1[1]);
        }
    }
    int oA = tx * 4, oB = 32 + tx * 4;
#pragma unroll
    for (int rr = 0; rr < 2; rr++) {
        int row = row0 + ((rr == 0) ? r0 : r1);
        if (row >= n_rows) continue;
        unsigned long long* accA = (rr == 0) ? aA0 : aA1;
        unsigned long long* accB = (rr == 0) ? aB0 : aB1;
        float* orow = out + (size_t)row * 64;
#pragma unroll
        for (int j = 0; j < 2; j++) {
            unsigned int lo, hi;
            UNPACK2(lo, hi, accA[j]);
            float2 s;
            s.x = __uint_as_float(lo) + Wb[oA + 2 * j + 0];
            s.y = __uint_as_float(hi) + Wb[oA + 2 * j + 1];
            *(float2*)(orow + oA + 2 * j) = s;
            UNPACK2(lo, hi, accB[j]);
            s.x = __uint_as_float(lo) + Wb[oB + 2 * j + 0];
            s.y = __uint_as_float(hi) + Wb[oB + 2 * j + 1];
            *(float2*)(orow + oB + 2 * j) = s;
        }
    }
}

// helper: 8B of half -> 4 floats
__device__ __forceinline__ void h4_to_f4(uint2 u, float& a, float& b, float& c, float& d)
{
    float2 f0 = __half22float2(u32_as_h2(u.x));
    float2 f1 = __half22float2(u32_as_h2(u.y));
    a = f0.x; b = f0.y; c = f1.x; d = f1.y;
}

// ---------------------------------------------------------------------------
// K_agg_e: warp per edge, contiguous half-ranges + int4 index loads,
// uint2 (4-feature) gathers, 16 lanes per row. (R12 version — validated win)
// ---------------------------------------------------------------------------
__global__ __launch_bounds__(256) void k_agg_e(const float* __restrict__ degV)
{
    const uint2* Xh = (const uint2*)g_Xh;
    int e    = (blockIdx.x * blockDim.x + threadIdx.x) >> 5;  // grid exact
    int lane = threadIdx.x & 31;
    int half_ = lane >> 4;
    int l    = lane & 15;
    int t = e / 10000;
    const float* degT = degV + t * NNODES;
    const int* mem = g_mem_e + (size_t)e * ECAP;
    int cnt = g_cur_e[e];
    if (cnt > ECAP) cnt = ECAP;
    int beg, end;
    half_range(cnt, half_, beg, end);
    float4 acc = make_float4(0.f, 0.f, 0.f, 0.f);
    float  sd  = 0.f;
    int i = beg;
    for (; i + 3 < end; i += 4) {
        int4 vv = *(const int4*)(mem + i);          // 1 LDG.128 (broadcast)
        float d0 = degT[vv.x], d1 = degT[vv.y], d2 = degT[vv.z], d3 = degT[vv.w];
        uint2 u0 = Xh[(size_t)vv.x * 16 + l];
        uint2 u1 = Xh[(size_t)vv.y * 16 + l];
        uint2 u2 = Xh[(size_t)vv.z * 16 + l];
        uint2 u3 = Xh[(size_t)vv.w * 16 + l];
        float ax, ay, az, aw;
        h4_to_f4(u0, ax, ay, az, aw);
        acc.x += d0 * ax; acc.y += d0 * ay; acc.z += d0 * az; acc.w += d0 * aw;
        h4_to_f4(u1, ax, ay, az, aw);
        acc.x += d1 * ax; acc.y += d1 * ay; acc.z += d1 * az; acc.w += d1 * aw;
        h4_to_f4(u2, ax, ay, az, aw);
        acc.x += d2 * ax; acc.y += d2 * ay; acc.z += d2 * az; acc.w += d2 * aw;
        h4_to_f4(u3, ax, ay, az, aw);
        acc.x += d3 * ax; acc.y += d3 * ay; acc.z += d3 * az; acc.w += d3 * aw;
        sd += d0 + d1 + d2 + d3;
    }
    for (; i < end; i++) {
        int v = mem[i];
        float d = degT[v];
        uint2 u = Xh[(size_t)v * 16 + l];
        float ax, ay, az, aw;
        h4_to_f4(u, ax, ay, az, aw);
        acc.x += d * ax; acc.y += d * ay; acc.z += d * az; acc.w += d * aw;
        sd += d;
    }
    acc.x += __shfl_xor_sync(0xFFFFFFFFu, acc.x, 16);
    acc.y += __shfl_xor_sync(0xFFFFFFFFu, acc.y, 16);
    acc.z += __shfl_xor_sync(0xFFFFFFFFu, acc.z, 16);
    acc.w += __shfl_xor_sync(0xFFFFFFFFu, acc.w, 16);
    sd    += __shfl_xor_sync(0xFFFFFFFFu, sd, 16);
    if (half_ == 0) {
        ((float4*)g_A)[(size_t)e * 16 + l] = acc;
        if (l == 0) {
            g_sdc[e] = make_float2(sd, (float)cnt);
            g_cur_e[e] = 0;   // restore zero invariant
        }
    }
}

// ---------------------------------------------------------------------------
// K_edge: Xe[e] = (W_{t+1} @ A[e] + b*sd[e]) / max(cnt,1). Writes fp16 Xe.
// ---------------------------------------------------------------------------
__global__ __launch_bounds__(256) void k_edge(
    const float* __restrict__ Ww, const float* __restrict__ Wb)
{
    const int CHUNKS = 157;
    int t     = blockIdx.x / CHUNKS;
    int chunk = blockIdx.x % CHUNKS;
    int base  = t * 10000 + chunk * 64;
    int limit = (t + 1) * 10000;

    __shared__ float Ws[64 * 68];
    __shared__ float As[64 * 68];
    const float* W = Ww + (size_t)(t + 1) * 4096;
    const float* b = Wb + (size_t)(t + 1) * 64;
    int tid = threadIdx.x;
    for (int idx = tid; idx < 1024; idx += 256) {
        int o = idx & 63, i4 = idx >> 6;
        float4 w = ((const float4*)W)[o * 16 + i4];
        Ws[(i4 * 4 + 0) * 68 + o] = w.x;
        Ws[(i4 * 4 + 1) * 68 + o] = w.y;
        Ws[(i4 * 4 + 2) * 68 + o] = w.z;
        Ws[(i4 * 4 + 3) * 68 + o] = w.w;
    }
    for (int idx = tid; idx < 1024; idx += 256) {
        int r = idx >> 4, j = idx & 15;
        int e = base + r;
        float4 v = make_float4(0.f, 0.f, 0.f, 0.f);
        if (e < limit) v = ((const float4*)g_A)[(size_t)e * 16 + j];
        *(float4*)(As + r * 68 + j * 4) = v;
    }
    __syncthreads();

    int tx = tid & 7, ty = tid >> 3;
    int r0 = 2 * ty, r1 = r0 + 1;
    unsigned long long aA0[2] = {0, 0}, aA1[2] = {0, 0};
    unsigned long long aB0[2] = {0, 0}, aB1[2] = {0, 0};
    const float* xr0 = As + r0 * 68;
    const float* xr1 = As + r1 * 68;
#pragma unroll
    for (int kk = 0; kk < 16; kk++) {
        float4 xa = *(const float4*)(xr0 + kk * 4);
        float4 xb = *(const float4*)(xr1 + kk * 4);
#pragma unroll
        for (int m = 0; m < 4; m++) {
            int k = kk * 4 + m;
            ulonglong2 wA = *(const ulonglong2*)(Ws + k * 68 + tx * 4);
            ulonglong2 wB = *(const ulonglong2*)(Ws + k * 68 + 32 + tx * 4);
            float x0v = (m == 0) ? xa.x : (m == 1) ? xa.y : (m == 2) ? xa.z : xa.w;
            float x1v = (m == 0) ? xb.x : (m == 1) ? xb.y : (m == 2) ? xb.z : xb.w;
            unsigned long long p0, p1;
            PACK_DUP(p0, x0v);
            PACK_DUP(p1, x1v);
            FMA2(aA0[0], p0, wA.x, aA0[0]);
            FMA2(aA0[1], p0, wA.y, aA0[1]);
            FMA2(aB0[0], p0, wB.x, aB0[0]);
            FMA2(aB0[1], p0, wB.y, aB0[1]);
            FMA2(aA1[0], p1, wA.x, aA1[0]);
            FMA2(aA1[1], p1, wA.y, aA1[1]);
            FMA2(aB1[0], p1, wB.x, aB1[0]);
            FMA2(aB1[1], p1, wB.y, aB1[1]);
        }
    }
    int oA = tx * 4, oB = 32 + tx * 4;
#pragma unroll
    for (int rr = 0; rr < 2; rr++) {
        int e = base + ((rr == 0) ? r0 : r1);
        if (e >= limit) continue;
        float2 sdc = g_sdc[e];
        float sd  = sdc.x;
        float inv = 1.0f / fmaxf(sdc.y, 1.0f);
        unsigned long long* accA = (rr == 0) ? aA0 : aA1;
        unsigned long long* accB = (rr == 0) ? aB0 : aB1;
        __half* orow = g_Xeh + (size_t)e * 64;
        unsigned int lo, hi;
        float sx, sy;
        UNPACK2(lo, hi, accA[0]);
        sx = (__uint_as_float(lo) + b[oA + 0] * sd) * inv;
        sy = (__uint_as_float(hi) + b[oA + 1] * sd) * inv;
        *(__half2*)(orow + oA + 0) = __floats2half2_rn(sx, sy);
        UNPACK2(lo, hi, accA[1]);
        sx = (__uint_as_float(lo) + b[oA + 2] * sd) * inv;
        sy = (__uint_as_float(hi) + b[oA + 3] * sd) * inv;
        *(__half2*)(orow + oA + 2) = __floats2half2_rn(sx, sy);
        UNPACK2(lo, hi, accB[0]);
        sx = (__uint_as_float(lo) + b[oB + 0] * sd) * inv;
        sy = (__uint_as_float(hi) + b[oB + 1] * sd) * inv;
        *(__half2*)(orow + oB + 0) = __floats2half2_rn(sx, sy);
        UNPACK2(lo, hi, accB[1]);
        sx = (__uint_as_float(lo) + b[oB + 2] * sd) * inv;
        sy = (__uint_as_float(hi) + b[oB + 3] * sd) * inv;
        *(__half2*)(orow + oB + 2) = __floats2half2_rn(sx, sy);
    }
}

// ---------------------------------------------------------------------------
// K_agg_v: warp per vertex, two 16-lane halves (stride-2 interleave), uint2
// gathers. (R11 version — best measured agg_v at 34.7us)
// ---------------------------------------------------------------------------
__global__ __launch_bounds__(256) void k_agg_v(float* __restrict__ out)
{
    const uint2* Xe = (const uint2*)g_Xeh;
    int v    = (blockIdx.x * blockDim.x + threadIdx.x) >> 5;
    int lane = threadIdx.x & 31;
    int half_ = lane >> 4;
    int l    = lane & 15;
    const int* mem = g_mem_v + (size_t)v * VCAP;
    int cnt = g_cur_v[v];
    if (cnt > VCAP) cnt = VCAP;
    float4 acc = make_float4(0.f, 0.f, 0.f, 0.f);
    if (half_ == 0) acc = ((const float4*)out)[(size_t)v * 16 + l];  // X0
    int i = half_;
    for (; i + 6 < cnt; i += 8) {
        int e0 = mem[i], e1 = mem[i + 2], e2 = mem[i + 4], e3 = mem[i + 6];
        uint2 u0 = Xe[(size_t)e0 * 16 + l];
        uint2 u1 = Xe[(size_t)e1 * 16 + l];
        uint2 u2 = Xe[(size_t)e2 * 16 + l];
        uint2 u3 = Xe[(size_t)e3 * 16 + l];
        float ax, ay, az, aw;
        h4_to_f4(u0, ax, ay, az, aw);
        acc.x += ax; acc.y += ay; acc.z += az; acc.w += aw;
        h4_to_f4(u1, ax, ay, az, aw);
        acc.x += ax; acc.y += ay; acc.z += az; acc.w += aw;
        h4_to_f4(u2, ax, ay, az, aw);
        acc.x += ax; acc.y += ay; acc.z += az; acc.w += aw;
        h4_to_f4(u3, ax, ay, az, aw);
        acc.x += ax; acc.y += ay; acc.z += az; acc.w += aw;
    }
    for (; i < cnt; i += 2) {
        int e = mem[i];
        uint2 u = Xe[(size_t)e * 16 + l];
        float ax, ay, az, aw;
        h4_to_f4(u, ax, ay, az, aw);
        acc.x += ax; acc.y += ay; acc.z += az; acc.w += aw;
    }
    acc.x += __shfl_xor_sync(0xFFFFFFFFu, acc.x, 16);
    acc.y += __shfl_xor_sync(0xFFFFFFFFu, acc.y, 16);
    acc.z += __shfl_xor_sync(0xFFFFFFFFu, acc.z, 16);
    acc.w += __shfl_xor_sync(0xFFFFFFFFu, acc.w, 16);
    float ss = acc.x * acc.x + acc.y * acc.y + acc.z * acc.z + acc.w * acc.w;
#pragma unroll
    for (int o = 8; o > 0; o >>= 1)
        ss += __shfl_xor_sync(0xFFFFFFFFu, ss, o);
    float rn = sqrtf(ss);
    float sc = (rn == 0.0f) ? 0.0f : 1.0f / rn;
    acc.x *= sc; acc.y *= sc; acc.z *= sc; acc.w *= sc;
    acc.x = (acc.x >= 0.f) ? acc.x : NEG_SLOPE * acc.x;
    acc.y = (acc.y >= 0.f) ? acc.y : NEG_SLOPE * acc.y;
    acc.z = (acc.z >= 0.f) ? acc.z : NEG_SLOPE * acc.z;
    acc.w = (acc.w >= 0.f) ? acc.w : NEG_SLOPE * acc.w;
    if (half_ == 0) {
        ((float4*)out)[(size_t)v * 16 + l] = acc;
        if (l == 0) g_cur_v[v] = 0;   // restore zero invariant
    }
}

// ---------------------------------------------------------------------------
extern "C" void kernel_launch(void* const* d_in, const int* in_sizes, int n_in,
                              void* d_out, int out_size)
{
    const float* X      = (const float*)d_in[0];   // [100000, 64] f32
    const float* degV   = (const float*)d_in[1];   // [3, 100000, 1] f32
    const float* Ww     = (const float*)d_in[2];   // [4, 64, 64] f32
    const float* Wb     = (const float*)d_in[3];   // [4, 64] f32
    const int*   vertex = (const int*)d_in[4];     // [1.6M] int32
    const int*   edges  = (const int*)d_in[5];     // [1.6M] int32
    float*       out    = (float*)d_out;           // [100000, 64] f32

    int n_pairs = in_sizes[4];

    k_x0h  <<<(NNODES + 63) / 64, 256>>>(X, Ww, Wb, vertex, edges, out, NNODES, n_pairs);
    k_agg_e<<<(NEDGES * 32) / 256, 256>>>(degV);
    k_edge <<<3 * 157, 256>>>(Ww, Wb);
    k_agg_v<<<(NNODES * 32) / 256, 256>>>(out);
}

// round 15
// speedup vs baseline: 1.6041x; 1.0133x over previous
#include <cuda_runtime.h>
#include <cuda_fp16.h>

// Problem constants
#define NNODES   100000
#define NEDGES   30000
#define NPAIRS   1600000
#define DFEAT    64
#define NEG_SLOPE 0.2f

#define ECAP 128     // max members per edge bucket (Poisson(53.3))
#define VCAP 64      // max members per vertex bucket (Poisson(16))

// Packed fp32x2 FMA (sm_100+): d = a*b + c per 32-bit lane
#define FMA2(d, a, b, c) \
    asm("fma.rn.f32x2 %0, %1, %2, %3;" : "=l"(d) : "l"(a), "l"(b), "l"(c))
#define PACK_DUP(out, v) \
    asm("mov.b64 %0, {%1, %1};" : "=l"(out) : "r"(__float_as_uint(v)))
#define UNPACK2(lo, hi, in) \
    asm("mov.b64 {%0, %1}, %2;" : "=r"(lo), "=r"(hi) : "l"(in))

__device__ __forceinline__ unsigned int h2_as_u32(__half2 h)
{
    unsigned int u; memcpy(&u, &h, 4); return u;
}
__device__ __forceinline__ __half2 u32_as_h2(unsigned int u)
{
    __half2 h; memcpy(&h, &u, 4); return h;
}

// Scratch (device globals: allocation-free).
// INVARIANT: g_cur_e / g_cur_v are ZERO at kernel_launch entry.
__device__ int    g_cur_e[NEDGES];
__device__ int    g_cur_v[NNODES];
__device__ int    g_mem_e[NEDGES * ECAP];   // vertex ids bucketed by edge
__device__ int    g_mem_v[NNODES * VCAP];   // edge ids bucketed by vertex
__device__ float  g_A   [NEDGES * DFEAT];   // per-edge input-space accumulators
__device__ float2 g_sdc [NEDGES];           // {sum(degV), count}
__device__ __half g_Xh  [NNODES * DFEAT];   // X staged as fp16
__device__ __half g_Xeh [NEDGES * DFEAT];   // per-edge output features (fp16)

// split [0,cnt) into two contiguous 4-aligned halves
__device__ __forceinline__ void half_range(int cnt, int half_, int& beg, int& end)
{
    int m = ((cnt + 1) >> 1);
    m = (m + 3) & ~3;
    if (m > cnt) m = cnt;
    beg = half_ ? m : 0;
    end = half_ ? cnt : m;
}

// ---------------------------------------------------------------------------
// K1 (x0h): bucket placement + X0 GEMM + fp16 staging of X.
// Placement: 4 consecutive pairs per thread via int4 loads (2 LDG.128),
// all 8 atomics issued back-to-back, stores last.
// ---------------------------------------------------------------------------
__global__ __launch_bounds__(256) void k_x0h(
    const float* __restrict__ X, const float* __restrict__ Ww,
    const float* __restrict__ Wb,
    const int* __restrict__ vertex, const int* __restrict__ edges,
    float* __restrict__ out, int n_rows, int n_pairs)
{
    int tid = threadIdx.x;

    // ---- bucket placement ----
    {
        int n4 = n_pairs >> 2;                      // int4 chunks
        int stride = gridDim.x * blockDim.x;
        for (int i4 = blockIdx.x * blockDim.x + tid; i4 < n4; i4 += stride) {
            int4 vv = ((const int4*)vertex)[i4];
            int4 ee = ((const int4*)edges)[i4];
            int pe0 = atomicAdd(&g_cur_e[ee.x], 1);
            int pe1 = atomicAdd(&g_cur_e[ee.y], 1);
            int pe2 = atomicAdd(&g_cur_e[ee.z], 1);
            int pe3 = atomicAdd(&g_cur_e[ee.w], 1);
            int pv0 = atomicAdd(&g_cur_v[vv.x], 1);
            int pv1 = atomicAdd(&g_cur_v[vv.y], 1);
            int pv2 = atomicAdd(&g_cur_v[vv.z], 1);
            int pv3 = atomicAdd(&g_cur_v[vv.w], 1);
            if (pe0 < ECAP) g_mem_e[ee.x * ECAP + pe0] = vv.x;
            if (pe1 < ECAP) g_mem_e[ee.y * ECAP + pe1] = vv.y;
            if (pe2 < ECAP) g_mem_e[ee.z * ECAP + pe2] = vv.z;
            if (pe3 < ECAP) g_mem_e[ee.w * ECAP + pe3] = vv.w;
            if (pv0 < VCAP) g_mem_v[vv.x * VCAP + pv0] = ee.x;
            if (pv1 < VCAP) g_mem_v[vv.y * VCAP + pv1] = ee.y;
            if (pv2 < VCAP) g_mem_v[vv.z * VCAP + pv2] = ee.z;
            if (pv3 < VCAP) g_mem_v[vv.w * VCAP + pv3] = ee.w;
        }
        // scalar tail (n_pairs % 4)
        int base = n4 << 2;
        int r = n_pairs - base;
        int gid = blockIdx.x * blockDim.x + tid;
        if (gid < r) {
            int i = base + gid;
            int v = vertex[i], e = edges[i];
            int pe = atomicAdd(&g_cur_e[e], 1);
            if (pe < ECAP) g_mem_e[e * ECAP + pe] = v;
            int pv = atomicAdd(&g_cur_v[v], 1);
            if (pv < VCAP) g_mem_v[v * VCAP + pv] = e;
        }
    }

    // ---- GEMM: X0 = X @ W0^T + b0 ----
    __shared__ float Ws[64 * 68];    // Ws[k*68+o] = W[o][k]
    __shared__ float Xs[64 * 68];    // Xs[r*68+k]
    for (int idx = tid; idx < 1024; idx += 256) {
        int o = idx & 63, i4 = idx >> 6;
        float4 w = ((const float4*)Ww)[o * 16 + i4];
        Ws[(i4 * 4 + 0) * 68 + o] = w.x;
        Ws[(i4 * 4 + 1) * 68 + o] = w.y;
        Ws[(i4 * 4 + 2) * 68 + o] = w.z;
        Ws[(i4 * 4 + 3) * 68 + o] = w.w;
    }
    int row0 = blockIdx.x * 64;
    for (int idx = tid; idx < 1024; idx += 256) {
        int r = idx >> 4, j = idx & 15;
        int row = row0 + r;
        float4 v = make_float4(0.f, 0.f, 0.f, 0.f);
        if (row < n_rows) v = ((const float4*)X)[(size_t)row * 16 + j];
        *(float4*)(Xs + r * 68 + j * 4) = v;
    }
    __syncthreads();

    // fp16 copy of X
    for (int idx = tid; idx < 1024; idx += 256) {
        int r = idx >> 4, j = idx & 15;
        int row = row0 + r;
        if (row < n_rows) {
            float4 v = *(const float4*)(Xs + r * 68 + j * 4);
            uint2 h;
            h.x = h2_as_u32(__floats2half2_rn(v.x, v.y));
            h.y = h2_as_u32(__floats2half2_rn(v.z, v.w));
            ((uint2*)g_Xh)[(size_t)row * 16 + j] = h;
        }
    }

    int tx = tid & 7, ty = tid >> 3;
    int r0 = 2 * ty, r1 = r0 + 1;
    unsigned long long aA0[2] = {0, 0}, aA1[2] = {0, 0};
    unsigned long long aB0[2] = {0, 0}, aB1[2] = {0, 0};
    const float* xr0 = Xs + r0 * 68;
    const float* xr1 = Xs + r1 * 68;
#pragma unroll
    for (int kk = 0; kk < 16; kk++) {
        float4 xa = *(const float4*)(xr0 + kk * 4);
        float4 xb = *(const float4*)(xr1 + kk * 4);
#pragma unroll
        for (int m = 0; m < 4; m++) {
            int k = kk * 4 + m;
            ulonglong2 wA = *(const ulonglong2*)(Ws + k * 68 + tx * 4);
            ulonglong2 wB = *(const ulonglong2*)(Ws + k * 68 + 32 + tx * 4);
            float x0v = (m == 0) ? xa.x : (m == 1) ? xa.y : (m == 2) ? xa.z : xa.w;
            float x1v = (m == 0) ? xb.x : (m == 1) ? xb.y : (m == 2) ? xb.z : xb.w;
            unsigned long long p0, p1;
            PACK_DUP(p0, x0v);
            PACK_DUP(p1, x1v);
            FMA2(aA0[0], p0, wA.x, aA0[0]);
            FMA2(aA0[1], p0, wA.y, aA0[1]);
            FMA2(aB0[0], p0, wB.x, aB0[0]);
            FMA2(aB0[1], p0, wB.y, aB0[1]);
            FMA2(aA1[0], p1, wA.x, aA1[0]);
            FMA2(aA1[1], p1, wA.y, aA1[1]);
            FMA2(aB1[0], p1, wB.x, aB1[0]);
            FMA2(aB1[1], p1, wB.y, aB1[1]);
        }
    }
    int oA = tx * 4, oB = 32 + tx * 4;
#pragma unroll
    for (int rr = 0; rr < 2; rr++) {
        int row = row0 + ((rr == 0) ? r0 : r1);
        if (row >= n_rows) continue;
        unsigned long long* accA = (rr == 0) ? aA0 : aA1;
        unsigned long long* accB = (rr == 0) ? aB0 : aB1;
        float* orow = out + (size_t)row * 64;
#pragma unroll
        for (int j = 0; j < 2; j++) {
            unsigned int lo, hi;
            UNPACK2(lo, hi, accA[j]);
            float2 s;
            s.x = __uint_as_float(lo) + Wb[oA + 2 * j + 0];
            s.y = __uint_as_float(hi) + Wb[oA + 2 * j + 1];
            *(float2*)(orow + oA + 2 * j) = s;
            UNPACK2(lo, hi, accB[j]);
            s.x = __uint_as_float(lo) + Wb[oB + 2 * j + 0];
            s.y = __uint_as_float(hi) + Wb[oB + 2 * j + 1];
            *(float2*)(orow + oB + 2 * j) = s;
        }
    }
}

// helper: 8B of half -> 4 floats
__device__ __forceinline__ void h4_to_f4(uint2 u, float& a, float& b, float& c, float& d)
{
    float2 f0 = __half22float2(u32_as_h2(u.x));
    float2 f1 = __half22float2(u32_as_h2(u.y));
    a = f0.x; b = f0.y; c = f1.x; d = f1.y;
}

// ---------------------------------------------------------------------------
// K_agg_e: warp per edge, contiguous half-ranges + int4 index loads,
// uint2 (4-feature) gathers, 16 lanes per row.
// ---------------------------------------------------------------------------
__global__ __launch_bounds__(256) void k_agg_e(const float* __restrict__ degV)
{
    const uint2* Xh = (const uint2*)g_Xh;
    int e    = (blockIdx.x * blockDim.x + threadIdx.x) >> 5;  // grid exact
    int lane = threadIdx.x & 31;
    int half_ = lane >> 4;
    int l    = lane & 15;
    int t = e / 10000;
    const float* degT = degV + t * NNODES;
    const int* mem = g_mem_e + (size_t)e * ECAP;
    int cnt = g_cur_e[e];
    if (cnt > ECAP) cnt = ECAP;
    int beg, end;
    half_range(cnt, half_, beg, end);
    float4 acc = make_float4(0.f, 0.f, 0.f, 0.f);
    float  sd  = 0.f;
    int i = beg;
    for (; i + 3 < end; i += 4) {
        int4 vv = *(const int4*)(mem + i);          // 1 LDG.128 (broadcast)
        float d0 = degT[vv.x], d1 = degT[vv.y], d2 = degT[vv.z], d3 = degT[vv.w];
        uint2 u0 = Xh[(size_t)vv.x * 16 + l];
        uint2 u1 = Xh[(size_t)vv.y * 16 + l];
        uint2 u2 = Xh[(size_t)vv.z * 16 + l];
        uint2 u3 = Xh[(size_t)vv.w * 16 + l];
        float ax, ay, az, aw;
        h4_to_f4(u0, ax, ay, az, aw);
        acc.x += d0 * ax; acc.y += d0 * ay; acc.z += d0 * az; acc.w += d0 * aw;
        h4_to_f4(u1, ax, ay, az, aw);
        acc.x += d1 * ax; acc.y += d1 * ay; acc.z += d1 * az; acc.w += d1 * aw;
        h4_to_f4(u2, ax, ay, az, aw);
        acc.x += d2 * ax; acc.y += d2 * ay; acc.z += d2 * az; acc.w += d2 * aw;
        h4_to_f4(u3, ax, ay, az, aw);
        acc.x += d3 * ax; acc.y += d3 * ay; acc.z += d3 * az; acc.w += d3 * aw;
        sd += d0 + d1 + d2 + d3;
    }
    for (; i < end; i++) {
        int v = mem[i];
        float d = degT[v];
        uint2 u = Xh[(size_t)v * 16 + l];
        float ax, ay, az, aw;
        h4_to_f4(u, ax, ay, az, aw);
        acc.x += d * ax; acc.y += d * ay; acc.z += d * az; acc.w += d * aw;
        sd += d;
    }
    acc.x += __shfl_xor_sync(0xFFFFFFFFu, acc.x, 16);
    acc.y += __shfl_xor_sync(0xFFFFFFFFu, acc.y, 16);
    acc.z += __shfl_xor_sync(0xFFFFFFFFu, acc.z, 16);
    acc.w += __shfl_xor_sync(0xFFFFFFFFu, acc.w, 16);
    sd    += __shfl_xor_sync(0xFFFFFFFFu, sd, 16);
    if (half_ == 0) {
        ((float4*)g_A)[(size_t)e * 16 + l] = acc;
        if (l == 0) {
            g_sdc[e] = make_float2(sd, (float)cnt);
            g_cur_e[e] = 0;   // restore zero invariant
        }
    }
}

// ---------------------------------------------------------------------------
// K_edge: Xe[e] = (W_{t+1} @ A[e] + b*sd[e]) / max(cnt,1). Writes fp16 Xe.
// ---------------------------------------------------------------------------
__global__ __launch_bounds__(256) void k_edge(
    const float* __restrict__ Ww, const float* __restrict__ Wb)
{
    const int CHUNKS = 157;
    int t     = blockIdx.x / CHUNKS;
    int chunk = blockIdx.x % CHUNKS;
    int base  = t * 10000 + chunk * 64;
    int limit = (t + 1) * 10000;

    __shared__ float Ws[64 * 68];
    __shared__ float As[64 * 68];
    const float* W = Ww + (size_t)(t + 1) * 4096;
    const float* b = Wb + (size_t)(t + 1) * 64;
    int tid = threadIdx.x;
    for (int idx = tid; idx < 1024; idx += 256) {
        int o = idx & 63, i4 = idx >> 6;
        float4 w = ((const float4*)W)[o * 16 + i4];
        Ws[(i4 * 4 + 0) * 68 + o] = w.x;
        Ws[(i4 * 4 + 1) * 68 + o] = w.y;
        Ws[(i4 * 4 + 2) * 68 + o] = w.z;
        Ws[(i4 * 4 + 3) * 68 + o] = w.w;
    }
    for (int idx = tid; idx < 1024; idx += 256) {
        int r = idx >> 4, j = idx & 15;
        int e = base + r;
        float4 v = make_float4(0.f, 0.f, 0.f, 0.f);
        if (e < limit) v = ((const float4*)g_A)[(size_t)e * 16 + j];
        *(float4*)(As + r * 68 + j * 4) = v;
    }
    __syncthreads();

    int tx = tid & 7, ty = tid >> 3;
    int r0 = 2 * ty, r1 = r0 + 1;
    unsigned long long aA0[2] = {0, 0}, aA1[2] = {0, 0};
    unsigned long long aB0[2] = {0, 0}, aB1[2] = {0, 0};
    const float* xr0 = As + r0 * 68;
    const float* xr1 = As + r1 * 68;
#pragma unroll
    for (int kk = 0; kk < 16; kk++) {
        float4 xa = *(const float4*)(xr0 + kk * 4);
        float4 xb = *(const float4*)(xr1 + kk * 4);
#pragma unroll
        for (int m = 0; m < 4; m++) {
            int k = kk * 4 + m;
            ulonglong2 wA = *(const ulonglong2*)(Ws + k * 68 + tx * 4);
            ulonglong2 wB = *(const ulonglong2*)(Ws + k * 68 + 32 + tx * 4);
            float x0v = (m == 0) ? xa.x : (m == 1) ? xa.y : (m == 2) ? xa.z : xa.w;
            float x1v = (m == 0) ? xb.x : (m == 1) ? xb.y : (m == 2) ? xb.z : xb.w;
            unsigned long long p0, p1;
            PACK_DUP(p0, x0v);
            PACK_DUP(p1, x1v);
            FMA2(aA0[0], p0, wA.x, aA0[0]);
            FMA2(aA0[1], p0, wA.y, aA0[1]);
            FMA2(aB0[0], p0, wB.x, aB0[0]);
            FMA2(aB0[1], p0, wB.y, aB0[1]);
            FMA2(aA1[0], p1, wA.x, aA1[0]);
            FMA2(aA1[1], p1, wA.y, aA1[1]);
            FMA2(aB1[0], p1, wB.x, aB1[0]);
            FMA2(aB1[1], p1, wB.y, aB1[1]);
        }
    }
    int oA = tx * 4, oB = 32 + tx * 4;
#pragma unroll
    for (int rr = 0; rr < 2; rr++) {
        int e = base + ((rr == 0) ? r0 : r1);
        if (e >= limit) continue;
        float2 sdc = g_sdc[e];
        float sd  = sdc.x;
        float inv = 1.0f / fmaxf(sdc.y, 1.0f);
        unsigned long long* accA = (rr == 0) ? aA0 : aA1;
        unsigned long long* accB = (rr == 0) ? aB0 : aB1;
        __half* orow = g_Xeh + (size_t)e * 64;
        unsigned int lo, hi;
        float sx, sy;
        UNPACK2(lo, hi, accA[0]);
        sx = (__uint_as_float(lo) + b[oA + 0] * sd) * inv;
        sy = (__uint_as_float(hi) + b[oA + 1] * sd) * inv;
        *(__half2*)(orow + oA + 0) = __floats2half2_rn(sx, sy);
        UNPACK2(lo, hi, accA[1]);
        sx = (__uint_as_float(lo) + b[oA + 2] * sd) * inv;
        sy = (__uint_as_float(hi) + b[oA + 3] * sd) * inv;
        *(__half2*)(orow + oA + 2) = __floats2half2_rn(sx, sy);
        UNPACK2(lo, hi, accB[0]);
        sx = (__uint_as_float(lo) + b[oB + 0] * sd) * inv;
        sy = (__uint_as_float(hi) + b[oB + 1] * sd) * inv;
        *(__half2*)(orow + oB + 0) = __floats2half2_rn(sx, sy);
        UNPACK2(lo, hi, accB[1]);
        sx = (__uint_as_float(lo) + b[oB + 2] * sd) * inv;
        sy = (__uint_as_float(hi) + b[oB + 3] * sd) * inv;
        *(__half2*)(orow + oB + 2) = __floats2half2_rn(sx, sy);
    }
}

// ---------------------------------------------------------------------------
// K_agg_v: warp per vertex, two 16-lane halves (stride-2 interleave), uint2
// gathers. (best measured agg_v)
// ---------------------------------------------------------------------------
__global__ __launch_bounds__(256) void k_agg_v(float* __restrict__ out)
{
    const uint2* Xe = (const uint2*)g_Xeh;
    int v    = (blockIdx.x * blockDim.x + threadIdx.x) >> 5;
    int lane = threadIdx.x & 31;
    int half_ = lane >> 4;
    int l    = lane & 15;
    const int* mem = g_mem_v + (size_t)v * VCAP;
    int cnt = g_cur_v[v];
    if (cnt > VCAP) cnt = VCAP;
    float4 acc = make_float4(0.f, 0.f, 0.f, 0.f);
    if (half_ == 0) acc = ((const float4*)out)[(size_t)v * 16 + l];  // X0
    int i = half_;
    for (; i + 6 < cnt; i += 8) {
        int e0 = mem[i], e1 = mem[i + 2], e2 = mem[i + 4], e3 = mem[i + 6];
        uint2 u0 = Xe[(size_t)e0 * 16 + l];
        uint2 u1 = Xe[(size_t)e1 * 16 + l];
        uint2 u2 = Xe[(size_t)e2 * 16 + l];
        uint2 u3 = Xe[(size_t)e3 * 16 + l];
        float ax, ay, az, aw;
        h4_to_f4(u0, ax, ay, az, aw);
        acc.x += ax; acc.y += ay; acc.z += az; acc.w += aw;
        h4_to_f4(u1, ax, ay, az, aw);
        acc.x += ax; acc.y += ay; acc.z += az; acc.w += aw;
        h4_to_f4(u2, ax, ay, az, aw);
        acc.x += ax; acc.y += ay; acc.z += az; acc.w += aw;
        h4_to_f4(u3, ax, ay, az, aw);
        acc.x += ax; acc.y += ay; acc.z += az; acc.w += aw;
    }
    for (; i < cnt; i += 2) {
        int e = mem[i];
        uint2 u = Xe[(size_t)e * 16 + l];
        float ax, ay, az, aw;
        h4_to_f4(u, ax, ay, az, aw);
        acc.x += ax; acc.y += ay; acc.z += az; acc.w += aw;
    }
    acc.x += __shfl_xor_sync(0xFFFFFFFFu, acc.x, 16);
    acc.y += __shfl_xor_sync(0xFFFFFFFFu, acc.y, 16);
    acc.z += __shfl_xor_sync(0xFFFFFFFFu, acc.z, 16);
    acc.w += __shfl_xor_sync(0xFFFFFFFFu, acc.w, 16);
    float ss = acc.x * acc.x + acc.y * acc.y + acc.z * acc.z + acc.w * acc.w;
#pragma unroll
    for (int o = 8; o > 0; o >>= 1)
        ss += __shfl_xor_sync(0xFFFFFFFFu, ss, o);
    float rn = sqrtf(ss);
    float sc = (rn == 0.0f) ? 0.0f : 1.0f / rn;
    acc.x *= sc; acc.y *= sc; acc.z *= sc; acc.w *= sc;
    acc.x = (acc.x >= 0.f) ? acc.x : NEG_SLOPE * acc.x;
    acc.y = (acc.y >= 0.f) ? acc.y : NEG_SLOPE * acc.y;
    acc.z = (acc.z >= 0.f) ? acc.z : NEG_SLOPE * acc.z;
    acc.w = (acc.w >= 0.f) ? acc.w : NEG_SLOPE * acc.w;
    if (half_ == 0) {
        ((float4*)out)[(size_t)v * 16 + l] = acc;
        if (l == 0) g_cur_v[v] = 0;   // restore zero invariant
    }
}

// ---------------------------------------------------------------------------
extern "C" void kernel_launch(void* const* d_in, const int* in_sizes, int n_in,
                              void* d_out, int out_size)
{
    const float* X      = (const float*)d_in[0];   // [100000, 64] f32
    const float* degV   = (const float*)d_in[1];   // [3, 100000, 1] f32
    const float* Ww     = (const float*)d_in[2];   // [4, 64, 64] f32
    const float* Wb     = (const float*)d_in[3];   // [4, 64] f32
    const int*   vertex = (const int*)d_in[4];     // [1.6M] int32
    const int*   edges  = (const int*)d_in[5];     // [1.6M] int32
    float*       out    = (float*)d_out;           // [100000, 64] f32

    int n_pairs = in_sizes[4];

    k_x0h  <<<(NNODES + 63) / 64, 256>>>(X, Ww, Wb, vertex, edges, out, NNODES, n_pairs);
    k_agg_e<<<(NEDGES * 32) / 256, 256>>>(degV);
    k_edge <<<3 * 157, 256>>>(Ww, Wb);
    k_agg_v<<<(NNODES * 32) / 256, 256>>>(out);
}